// round 14
// baseline (speedup 1.0000x reference)
#include <cuda_runtime.h>
#include <math.h>

// Problem constants (fixed shapes per reference)
#define NN 100000
#define BB 1024
#define LAT 128
#define INDIM 384      // NODE_DIM + 2*LATENT
#define FFNIN 512      // LATENT + IN_DIM
#define CAP 512        // neighbor list capacity (mean ~50)
#define GQ 8           // queries per epi block
#define PREPB 256      // prep-GEMM blocks inside k_main

// Scratch (device globals; no allocation allowed)
__device__ float g_qk[BB * INDIM];
__device__ float g_hpart[BB * LAT];     // W1b @ q_input + b1
__device__ float g_acc[BB * INDIM];     // softmax-weighted kv sum
__device__ float g_Wqk[INDIM * INDIM];  // Wk^T @ Wq
__device__ float g_bqk[INDIM];          // Wk^T @ bq
__device__ float g_Wfold[LAT * INDIM];  // W1a @ Wv
__device__ float g_cvec[LAT];           // W1a @ bv
__device__ int   g_list[BB * CAP];
__device__ int   g_cnt[BB];

// Merge two partial-sum arrays across xor-lane distance `bit`
__device__ __forceinline__ float mrg(float a, float b, int bit, int lane) {
    float keep = (lane & bit) ? b : a;
    float send = (lane & bit) ? a : b;
    return keep + __shfl_xor_sync(0xffffffffu, send, bit);
}

// ---------------------------------------------------------------------------
// Kernel 0: weight precompute (R10-verbatim, correctness-proven).
//   bi <  96: Wqk rows o=bi*4..+3:  Wqk[o][c] = sum_j Wk[j][o] Wq[j][c]; bqk
//   bi >= 96: Wfold rows o=(bi-96)*4: Wfold[o][c] = sum_j W1a[o][j] Wv[j][c]; cvec
// ---------------------------------------------------------------------------
__global__ void __launch_bounds__(384) k_weights(
    const float* __restrict__ Wq, const float* __restrict__ bq,
    const float* __restrict__ Wk, const float* __restrict__ Wv,
    const float* __restrict__ bv, const float* __restrict__ W1)
{
    int bi = blockIdx.x, t = threadIdx.x, lane = t & 31, w = t >> 5;
    __shared__ float wcol[4][LAT];
    bool qkpart = (bi < 96);
    int o0 = qkpart ? bi * 4 : (bi - 96) * 4;

    if (t < LAT) {
        if (qkpart) {
            float4 v = *(const float4*)&Wk[(size_t)t * INDIM + o0];
            wcol[0][t] = v.x; wcol[1][t] = v.y; wcol[2][t] = v.z; wcol[3][t] = v.w;
        } else {
            #pragma unroll
            for (int r = 0; r < 4; r++)
                wcol[r][t] = W1[(size_t)(o0 + r) * FFNIN + t];
        }
    }
    __syncthreads();

    if (w < 4) {
        const float* bvec = qkpart ? bq : bv;
        float v = 0.f;
        #pragma unroll
        for (int i = 0; i < 4; i++) v = fmaf(wcol[w][lane + 32 * i], bvec[lane + 32 * i], v);
        #pragma unroll
        for (int off = 16; off; off >>= 1) v += __shfl_xor_sync(0xffffffffu, v, off);
        if (lane == 0) {
            if (qkpart) g_bqk[o0 + w] = v;
            else        g_cvec[o0 + w] = v;
        }
    }

    const float* M = qkpart ? Wq : Wv;
    float a0 = 0.f, a1 = 0.f, a2 = 0.f, a3 = 0.f;
    #pragma unroll 4
    for (int j = 0; j < LAT; j++) {
        float mv = M[(size_t)j * INDIM + t];
        a0 = fmaf(wcol[0][j], mv, a0);
        a1 = fmaf(wcol[1][j], mv, a1);
        a2 = fmaf(wcol[2][j], mv, a2);
        a3 = fmaf(wcol[3][j], mv, a3);
    }
    float* dst = qkpart ? g_Wqk : g_Wfold;
    dst[(size_t)(o0 + 0) * INDIM + t] = a0;
    dst[(size_t)(o0 + 1) * INDIM + t] = a1;
    dst[(size_t)(o0 + 2) * INDIM + t] = a2;
    dst[(size_t)(o0 + 3) * INDIM + t] = a3;
}

// Shared-memory union for the fat kernel
struct SmemPrep {
    float qin[16][INDIM];     // 24576 B
    float w[32][132];         // 16896 B (132: float4-aligned, conflict-free)
    int   sidx[16];
};
struct SmemScan {
    int idx[CAP];
    int cnt;
};
union SmemU {
    SmemPrep p;
    SmemScan s;
};

#define PROC4(u, base) \
    if (u.x | u.y | u.z | u.w) { \
        if (u.x) { int sl = atomicAdd(cntp, 1); if (sl < CAP) idxp[sl] = (base) * 4 + 0; } \
        if (u.y) { int sl = atomicAdd(cntp, 1); if (sl < CAP) idxp[sl] = (base) * 4 + 1; } \
        if (u.z) { int sl = atomicAdd(cntp, 1); if (sl < CAP) idxp[sl] = (base) * 4 + 2; } \
        if (u.w) { int sl = atomicAdd(cntp, 1); if (sl < CAP) idxp[sl] = (base) * 4 + 3; } }

// ---------------------------------------------------------------------------
// FAT kernel: blocks [0,256) = prep GEMM ; [256, 1280) = scan.
// Prep block bi: 16 queries (qt=bi>>2) x 128 outputs (ot=bi&3) of the
// combined 512-output matrix [Wqk (384 rows) ; W1b (128 rows)].
// No inter-stage dependencies -> short critical path; scan dominates.
// ---------------------------------------------------------------------------
__global__ void __launch_bounds__(512, 2) k_main(
    const float* __restrict__ x, const float* __restrict__ mem,
    const float* __restrict__ tart, const int* __restrict__ tidx,
    const float* __restrict__ W1, const float* __restrict__ b1,
    const unsigned char* __restrict__ maskb)
{
    __shared__ SmemU su;
    int t = threadIdx.x;

    if (blockIdx.x >= PREPB) {
        // ================= SCAN PATH (512 threads, R12-proven) =============
        int b = blockIdx.x - PREPB;
        int* idxp = su.s.idx;
        int* cntp = &su.s.cnt;
        if (t == 0) *cntp = 0;
        __syncthreads();

        const uint4* row = (const uint4*)(maskb + (size_t)b * NN * 4);
        const int NW = NN / 4;                    // 25000 uint4
        int i = t;
        for (; i + 1536 < NW; i += 2048) {
            uint4 a  = row[i];
            uint4 b4 = row[i + 512];
            uint4 c4 = row[i + 1024];
            uint4 d4 = row[i + 1536];
            PROC4(a, i) PROC4(b4, i + 512) PROC4(c4, i + 1024) PROC4(d4, i + 1536)
        }
        for (; i < NW; i += 512) { uint4 u = row[i]; PROC4(u, i) }

        __syncthreads();
        int cnt = min(*cntp, CAP);
        if (cnt == 0) {
            if (t == 0) { g_list[b * CAP] = tidx[b]; g_cnt[b] = 1; }
            return;
        }
        for (int m2 = t; m2 < cnt; m2 += 512) g_list[b * CAP + m2] = idxp[m2];
        if (t == 0) g_cnt[b] = cnt;
        return;
    }

    // ================= PREP GEMM PATH =================
    int qt = blockIdx.x >> 2, ot = blockIdx.x & 3;
    int b0 = qt * 16, o0 = ot * 128;
    int q = t >> 5, ogrp = t & 31;          // thread: query q, outputs ogrp*4..+3

    if (t < 16) su.p.sidx[t] = tidx[b0 + t];
    __syncthreads();

    // load qin for 16 queries (float4, coalesced)
    for (int m2 = t; m2 < 16 * 96; m2 += 512) {
        int qq = m2 / 96, c4 = m2 % 96;
        float4 v;
        if (c4 < 32)      v = ((const float4*)(x    + (size_t)su.p.sidx[qq] * LAT))[c4];
        else if (c4 < 64) v = ((const float4*)(mem  + (size_t)su.p.sidx[qq] * LAT))[c4 - 32];
        else              v = ((const float4*)(tart + (size_t)(b0 + qq) * LAT))[c4 - 64];
        *(float4*)&su.p.qin[qq][c4 * 4] = v;
    }

    float acc0 = 0.f, acc1 = 0.f, acc2 = 0.f, acc3 = 0.f;
    bool qkpart = (o0 < INDIM);             // ot<3: Wqk rows; ot==3: W1b rows

    for (int kt = 0; kt < INDIM; kt += 32) {
        __syncthreads();
        // stage weight tile w[k][o'] = W[o0+o'][kt+k], 4096 elems, 8 per thread
        for (int idx = t; idx < 4096; idx += 512) {
            int op = idx >> 5, k = idx & 31;
            int row = o0 + op;
            float wv = qkpart ? g_Wqk[(size_t)row * INDIM + kt + k]
                              : W1[(size_t)(row - INDIM) * FFNIN + LAT + kt + k];
            su.p.w[k][op] = wv;
        }
        __syncthreads();
        #pragma unroll
        for (int k = 0; k < 32; k++) {
            float a = su.p.qin[q][kt + k];
            float4 wv = *(const float4*)&su.p.w[k][ogrp * 4];
            acc0 = fmaf(a, wv.x, acc0);
            acc1 = fmaf(a, wv.y, acc1);
            acc2 = fmaf(a, wv.z, acc2);
            acc3 = fmaf(a, wv.w, acc3);
        }
    }

    int b = b0 + q;
    int o = o0 + ogrp * 4;
    if (qkpart) {
        g_qk[(size_t)b * INDIM + o + 0] = acc0 + g_bqk[o + 0];
        g_qk[(size_t)b * INDIM + o + 1] = acc1 + g_bqk[o + 1];
        g_qk[(size_t)b * INDIM + o + 2] = acc2 + g_bqk[o + 2];
        g_qk[(size_t)b * INDIM + o + 3] = acc3 + g_bqk[o + 3];
    } else {
        int oh = o - INDIM;
        g_hpart[(size_t)b * LAT + oh + 0] = acc0 + b1[oh + 0];
        g_hpart[(size_t)b * LAT + oh + 1] = acc1 + b1[oh + 1];
        g_hpart[(size_t)b * LAT + oh + 2] = acc2 + b1[oh + 2];
        g_hpart[(size_t)b * LAT + oh + 3] = acc3 + b1[oh + 3];
    }
}

// ---------------------------------------------------------------------------
// Kernel 2: PURE gather + online softmax -> g_acc (R10/R13-proven, 26.6us).
// ---------------------------------------------------------------------------
__global__ void __launch_bounds__(512) k_gather(
    const float* __restrict__ x, const float* __restrict__ mem,
    const float* __restrict__ dt)
{
    int b = blockIdx.x, t = threadIdx.x, lane = t & 31, w = t >> 5;
    __shared__ float s_qk[INDIM];
    __shared__ float s_part[16][INDIM];
    __shared__ float s_m[16], s_l[16];

    if (t < INDIM) s_qk[t] = g_qk[(size_t)b * INDIM + t];
    __syncthreads();
    int cnt = g_cnt[b];
    const float scale = 0.08838834764831845f;   // 1/sqrt(128)

    float m = -INFINITY, l = 0.f;
    float racc[12];
    #pragma unroll
    for (int r = 0; r < 12; r++) racc[r] = 0.f;

    int p = w;
    float rowv[12];
    if (p < cnt) {
        int n = g_list[b * CAP + p];
        const float* px = x + (size_t)n * LAT;
        const float* pm = mem + (size_t)n * LAT;
        const float* pd = dt + (size_t)n * LAT;
        #pragma unroll
        for (int r = 0; r < 4; r++) rowv[r]     = px[lane + 32 * r];
        #pragma unroll
        for (int r = 0; r < 4; r++) rowv[4 + r] = pm[lane + 32 * r];
        #pragma unroll
        for (int r = 0; r < 4; r++) rowv[8 + r] = pd[lane + 32 * r];
    }
    while (p < cnt) {
        int pn = p + 16;
        float rnext[12];
        if (pn < cnt) {
            int n = g_list[b * CAP + pn];
            const float* px = x + (size_t)n * LAT;
            const float* pm = mem + (size_t)n * LAT;
            const float* pd = dt + (size_t)n * LAT;
            #pragma unroll
            for (int r = 0; r < 4; r++) rnext[r]     = px[lane + 32 * r];
            #pragma unroll
            for (int r = 0; r < 4; r++) rnext[4 + r] = pm[lane + 32 * r];
            #pragma unroll
            for (int r = 0; r < 4; r++) rnext[8 + r] = pd[lane + 32 * r];
        }
        float dot = 0.f;
        #pragma unroll
        for (int r = 0; r < 12; r++) dot = fmaf(rowv[r], s_qk[32 * r + lane], dot);
        #pragma unroll
        for (int off = 16; off; off >>= 1) dot += __shfl_xor_sync(0xffffffffu, dot, off);
        float s = dot * scale;                  // q.bk dropped (softmax-invariant)
        float mnew = fmaxf(m, s);
        float corr = __expf(m - mnew);
        float e = __expf(s - mnew);
        l = l * corr + e;
        m = mnew;
        #pragma unroll
        for (int r = 0; r < 12; r++) racc[r] = fmaf(racc[r], corr, e * rowv[r]);
        #pragma unroll
        for (int r = 0; r < 12; r++) rowv[r] = rnext[r];
        p = pn;
    }
    #pragma unroll
    for (int r = 0; r < 12; r++) s_part[w][32 * r + lane] = racc[r];
    if (lane == 0) { s_m[w] = m; s_l[w] = l; }
    __syncthreads();

    float M = s_m[0];
    #pragma unroll
    for (int i = 1; i < 16; i++) M = fmaxf(M, s_m[i]);
    float L = 0.f;
    float ef[16];
    #pragma unroll
    for (int i = 0; i < 16; i++) { ef[i] = __expf(s_m[i] - M); L += s_l[i] * ef[i]; }
    float invL = 1.f / L;
    if (t < INDIM) {
        float sum = 0.f;
        #pragma unroll
        for (int i = 0; i < 16; i++) sum = fmaf(s_part[i][t], ef[i], sum);
        g_acc[(size_t)b * INDIM + t] = sum * invL;
    }
}

// ---------------------------------------------------------------------------
// Kernel 3: folded epilogue (R13-proven). 128 blocks x 512, GQ=8.
//   h = relu(Wfold@acc + hpart + cvec) ; out = W2@h + b2
// ---------------------------------------------------------------------------
__global__ void __launch_bounds__(512, 2) k_epi(
    const float* __restrict__ W2, const float* __restrict__ b2,
    float* __restrict__ out)
{
    int b0 = blockIdx.x * GQ;
    int t = threadIdx.x, lane = t & 31, w = t >> 5;
    __shared__ float acc[GQ][INDIM];
    __shared__ float hp[GQ][LAT];
    __shared__ float h[GQ][LAT];

    for (int m = t; m < GQ * 96; m += 512) {
        int q = m / 96, c4 = m % 96;
        *(float4*)&acc[q][c4 * 4] = *(const float4*)&g_acc[(size_t)(b0 + q) * INDIM + c4 * 4];
    }
    for (int m = t; m < GQ * LAT; m += 512) {
        int q = m >> 7, o = m & 127;
        hp[q][o] = g_hpart[(size_t)(b0 + q) * LAT + o] + g_cvec[o];
    }
    __syncthreads();

    // stage 1: h = relu(Wfold @ acc + hp)  (2 groups of 4 queries)
    for (int oi = 0; oi < 8; oi++) {
        int o = w * 8 + oi;
        const float* wr = g_Wfold + (size_t)o * INDIM;
        float wreg[12];
        #pragma unroll
        for (int r = 0; r < 12; r++) wreg[r] = wr[lane + 32 * r];
        #pragma unroll
        for (int g = 0; g < 2; g++) {
            float p[4];
            #pragma unroll
            for (int qq = 0; qq < 4; qq++) {
                float s = 0.f;
                #pragma unroll
                for (int r = 0; r < 12; r++)
                    s = fmaf(wreg[r], acc[g * 4 + qq][lane + 32 * r], s);
                p[qq] = s;
            }
            float a0 = mrg(p[0], p[1], 16, lane), a1 = mrg(p[2], p[3], 16, lane);
            float c0 = mrg(a0, a1, 8, lane);
            c0 += __shfl_xor_sync(0xffffffffu, c0, 4);
            c0 += __shfl_xor_sync(0xffffffffu, c0, 2);
            c0 += __shfl_xor_sync(0xffffffffu, c0, 1);
            if ((lane & 7) == 0) {
                int q = g * 4 + ((lane >> 4) & 1) + ((lane >> 3) & 1) * 2;
                h[q][o] = fmaxf(c0 + hp[q][o], 0.f);
            }
        }
    }
    __syncthreads();

    // stage 2: out = W2 @ h + b2
    for (int oi = 0; oi < 8; oi++) {
        int o = w * 8 + oi;
        const float* wr = W2 + (size_t)o * LAT;
        float wreg[4];
        #pragma unroll
        for (int r = 0; r < 4; r++) wreg[r] = wr[lane + 32 * r];
        float bias = b2[o];
        #pragma unroll
        for (int g = 0; g < 2; g++) {
            float p[4];
            #pragma unroll
            for (int qq = 0; qq < 4; qq++) {
                float s = 0.f;
                #pragma unroll
                for (int r = 0; r < 4; r++)
                    s = fmaf(wreg[r], h[g * 4 + qq][lane + 32 * r], s);
                p[qq] = s;
            }
            float a0 = mrg(p[0], p[1], 16, lane), a1 = mrg(p[2], p[3], 16, lane);
            float c0 = mrg(a0, a1, 8, lane);
            c0 += __shfl_xor_sync(0xffffffffu, c0, 4);
            c0 += __shfl_xor_sync(0xffffffffu, c0, 2);
            c0 += __shfl_xor_sync(0xffffffffu, c0, 1);
            if ((lane & 7) == 0) {
                int q = g * 4 + ((lane >> 4) & 1) + ((lane >> 3) & 1) * 2;
                out[(size_t)(b0 + q) * LAT + o] = c0 + bias;
            }
        }
    }
}

// ---------------------------------------------------------------------------
extern "C" void kernel_launch(void* const* d_in, const int* in_sizes, int n_in,
                              void* d_out, int out_size)
{
    const float* x    = (const float*)d_in[0];
    const float* mem  = (const float*)d_in[1];
    const float* dt   = (const float*)d_in[2];
    const float* tart = (const float*)d_in[3];
    const unsigned char* mask = (const unsigned char*)d_in[4];
    const int*   tidx = (const int*)d_in[5];
    const float* Wq = (const float*)d_in[6];
    const float* bq = (const float*)d_in[7];
    const float* Wk = (const float*)d_in[8];
    // bk (d_in[9]) unused: q.bk cancels in softmax
    const float* Wv = (const float*)d_in[10];
    const float* bv = (const float*)d_in[11];
    const float* W1 = (const float*)d_in[12];
    const float* b1 = (const float*)d_in[13];
    const float* W2 = (const float*)d_in[14];
    const float* b2 = (const float*)d_in[15];
    float* out = (float*)d_out;

    // Single stream: weights -> fat(prep GEMM + scan) -> gather -> epi.
    k_weights<<<128, 384>>>(Wq, bq, Wk, Wv, bv, W1);
    k_main<<<PREPB + BB, 512>>>(x, mem, tart, tidx, W1, b1, mask);
    k_gather<<<BB, 512>>>(x, mem, dt);
    k_epi<<<BB / GQ, 512>>>(W2, b2, out);
}

// round 15
// speedup vs baseline: 1.2253x; 1.2253x over previous
#include <cuda_runtime.h>
#include <math.h>

// Problem constants (fixed shapes per reference)
#define NN 100000
#define BB 1024
#define LAT 128
#define INDIM 384      // NODE_DIM + 2*LATENT
#define FFNIN 512      // LATENT + IN_DIM
#define CAP 512        // neighbor list capacity (mean ~50)
#define GQ 8           // queries per prep block
#define EQ 4           // queries per epi block
#define PREPB 128      // number of prep blocks (BB/GQ)

// Scratch (device globals; no allocation allowed)
__device__ float g_qk[BB * INDIM];
__device__ float g_hpart[BB * LAT];     // W1b @ q_input + b1
__device__ float g_acc[BB * INDIM];     // softmax-weighted kv sum
__device__ float g_Wfold[LAT * INDIM];  // W1a @ Wv
__device__ float g_cvec[LAT];           // W1a @ bv
__device__ int   g_list[BB * CAP];
__device__ int   g_cnt[BB];

// Merge two partial-sum arrays across xor-lane distance `bit`
__device__ __forceinline__ float mrg(float a, float b, int bit, int lane) {
    float keep = (lane & bit) ? b : a;
    float send = (lane & bit) ? a : b;
    return keep + __shfl_xor_sync(0xffffffffu, send, bit);
}

// Shared-memory union: prep path needs ~41.5KB, scan path ~2KB.
struct SmemPrep {
    float qin[GQ][INDIM];
    float qsm[GQ][LAT];
    float wk_sm[16][INDIM];
    float w1a[LAT];
    float cvec;
    int   sidx[GQ];
};
struct SmemScan {
    int idx[CAP];
    int cnt;
};
union SmemU {
    SmemPrep p;
    SmemScan s;
};

#define PROC4(u, base) \
    if (u.x | u.y | u.z | u.w) { \
        if (u.x) { int sl = atomicAdd(cntp, 1); if (sl < CAP) idxp[sl] = (base) * 4 + 0; } \
        if (u.y) { int sl = atomicAdd(cntp, 1); if (sl < CAP) idxp[sl] = (base) * 4 + 1; } \
        if (u.z) { int sl = atomicAdd(cntp, 1); if (sl < CAP) idxp[sl] = (base) * 4 + 2; } \
        if (u.w) { int sl = atomicAdd(cntp, 1); if (sl < CAP) idxp[sl] = (base) * 4 + 3; } }

// ---------------------------------------------------------------------------
// FAT kernel (R12/R13-proven): blocks [0,128) = prep ; [128, 1152) = scan.
// ---------------------------------------------------------------------------
__global__ void __launch_bounds__(512, 2) k_main(
    const float* __restrict__ x, const float* __restrict__ mem,
    const float* __restrict__ tart, const int* __restrict__ tidx,
    const float* __restrict__ Wq, const float* __restrict__ bq,
    const float* __restrict__ Wk, const float* __restrict__ W1,
    const float* __restrict__ b1, const float* __restrict__ Wv,
    const float* __restrict__ bv, const unsigned char* __restrict__ maskb)
{
    __shared__ SmemU su;
    int t = threadIdx.x, lane = t & 31, w = t >> 5;

    if (blockIdx.x >= PREPB) {
        // ================= SCAN PATH (512 threads) =================
        int b = blockIdx.x - PREPB;
        int* idxp = su.s.idx;
        int* cntp = &su.s.cnt;
        if (t == 0) *cntp = 0;
        __syncthreads();

        const uint4* row = (const uint4*)(maskb + (size_t)b * NN * 4);
        const int NW = NN / 4;                    // 25000 uint4
        int i = t;
        for (; i + 1536 < NW; i += 2048) {
            uint4 a  = row[i];
            uint4 b4 = row[i + 512];
            uint4 c4 = row[i + 1024];
            uint4 d4 = row[i + 1536];
            PROC4(a, i) PROC4(b4, i + 512) PROC4(c4, i + 1024) PROC4(d4, i + 1536)
        }
        for (; i < NW; i += 512) { uint4 u = row[i]; PROC4(u, i) }

        __syncthreads();
        int cnt = min(*cntp, CAP);
        if (cnt == 0) {
            if (t == 0) { g_list[b * CAP] = tidx[b]; g_cnt[b] = 1; }
            return;
        }
        for (int m2 = t; m2 < cnt; m2 += 512) g_list[b * CAP + m2] = idxp[m2];
        if (t == 0) g_cnt[b] = cnt;
        return;
    }

    // ================= PREP PATH =================
    int b0 = blockIdx.x * GQ;
    if (t < GQ) su.p.sidx[t] = tidx[b0 + t];
    if (t < LAT) su.p.w1a[t] = W1[(size_t)blockIdx.x * FFNIN + t];
    __syncthreads();

    // Wfold row: Wfold[o][c] = sum_j w1a[j] * Wv[j][c]  (o = blockIdx)
    if (t < INDIM) {
        float s = 0.f;
        #pragma unroll 8
        for (int j = 0; j < LAT; j++) s = fmaf(su.p.w1a[j], Wv[(size_t)j * INDIM + t], s);
        g_Wfold[(size_t)blockIdx.x * INDIM + t] = s;
    }
    // cvec[o] = w1a . bv
    if (w == 15) {
        float v = 0.f;
        #pragma unroll
        for (int r = 0; r < 4; r++) v = fmaf(su.p.w1a[lane + 32 * r], bv[lane + 32 * r], v);
        #pragma unroll
        for (int off = 16; off; off >>= 1) v += __shfl_xor_sync(0xffffffffu, v, off);
        if (lane == 0) su.p.cvec = v;
    }

    // gather q_input
    for (int m2 = t; m2 < GQ * 96; m2 += 512) {
        int q = m2 / 96, c4 = m2 % 96;
        float4 v;
        if (c4 < 32)      v = ((const float4*)(x    + (size_t)su.p.sidx[q] * LAT))[c4];
        else if (c4 < 64) v = ((const float4*)(mem  + (size_t)su.p.sidx[q] * LAT))[c4 - 32];
        else              v = ((const float4*)(tart + (size_t)(b0 + q) * LAT))[c4 - 64];
        *(float4*)&su.p.qin[q][c4 * 4] = v;
    }
    __syncthreads();

    // q = Wq @ qin + bq  (16 warps x 8 outputs; 2 groups of 4 queries)
    for (int oi = 0; oi < 8; oi++) {
        int o = w * 8 + oi;
        const float* wr = Wq + (size_t)o * INDIM;
        float wreg[12];
        #pragma unroll
        for (int r = 0; r < 12; r++) wreg[r] = wr[lane + 32 * r];
        float bias = bq[o];
        #pragma unroll
        for (int g = 0; g < 2; g++) {
            float p[4];
            #pragma unroll
            for (int qq = 0; qq < 4; qq++) {
                float s = 0.f;
                #pragma unroll
                for (int r = 0; r < 12; r++)
                    s = fmaf(wreg[r], su.p.qin[g * 4 + qq][lane + 32 * r], s);
                p[qq] = s;
            }
            float a0 = mrg(p[0], p[1], 16, lane), a1 = mrg(p[2], p[3], 16, lane);
            float c0 = mrg(a0, a1, 8, lane);
            c0 += __shfl_xor_sync(0xffffffffu, c0, 4);
            c0 += __shfl_xor_sync(0xffffffffu, c0, 2);
            c0 += __shfl_xor_sync(0xffffffffu, c0, 1);
            if ((lane & 7) == 0) {
                int q = g * 4 + ((lane >> 4) & 1) + ((lane >> 3) & 1) * 2;
                su.p.qsm[q][o] = c0 + bias;
            }
        }
    }

    // hpart = W1b @ qin + b1
    for (int oi = 0; oi < 8; oi++) {
        int o = w * 8 + oi;
        const float* wr = W1 + (size_t)o * FFNIN + LAT;
        float wreg[12];
        #pragma unroll
        for (int r = 0; r < 12; r++) wreg[r] = wr[lane + 32 * r];
        float bias = b1[o];
        #pragma unroll
        for (int g = 0; g < 2; g++) {
            float p[4];
            #pragma unroll
            for (int qq = 0; qq < 4; qq++) {
                float s = 0.f;
                #pragma unroll
                for (int r = 0; r < 12; r++)
                    s = fmaf(wreg[r], su.p.qin[g * 4 + qq][lane + 32 * r], s);
                p[qq] = s;
            }
            float a0 = mrg(p[0], p[1], 16, lane), a1 = mrg(p[2], p[3], 16, lane);
            float c0 = mrg(a0, a1, 8, lane);
            c0 += __shfl_xor_sync(0xffffffffu, c0, 4);
            c0 += __shfl_xor_sync(0xffffffffu, c0, 2);
            c0 += __shfl_xor_sync(0xffffffffu, c0, 1);
            if ((lane & 7) == 0) {
                int q = g * 4 + ((lane >> 4) & 1) + ((lane >> 3) & 1) * 2;
                g_hpart[(size_t)(b0 + q) * LAT + o] = c0 + bias;
            }
        }
    }
    __syncthreads();

    // qk = Wk^T q  (smem-staged Wk tiles)
    {
        float acc[GQ];
        #pragma unroll
        for (int q = 0; q < GQ; q++) acc[q] = 0.f;
        for (int j0 = 0; j0 < LAT; j0 += 16) {
            __syncthreads();
            for (int m2 = t; m2 < 16 * 96; m2 += 512) {
                int jj = m2 / 96, c4 = m2 % 96;
                *(float4*)&su.p.wk_sm[jj][c4 * 4] =
                    ((const float4*)(Wk + (size_t)(j0 + jj) * INDIM))[c4];
            }
            __syncthreads();
            if (t < INDIM) {
                #pragma unroll
                for (int jj = 0; jj < 16; jj++) {
                    float wv = su.p.wk_sm[jj][t];
                    #pragma unroll
                    for (int q = 0; q < GQ; q++)
                        acc[q] = fmaf(su.p.qsm[q][j0 + jj], wv, acc[q]);
                }
            }
        }
        if (t < INDIM) {
            #pragma unroll
            for (int q = 0; q < GQ; q++) g_qk[(size_t)(b0 + q) * INDIM + t] = acc[q];
        }
    }
    if (t == 0) g_cvec[blockIdx.x] = su.p.cvec;
}

// ---------------------------------------------------------------------------
// Kernel 2: PURE gather + online softmax -> g_acc (R10/R13-proven, 26.6us).
// ---------------------------------------------------------------------------
__global__ void __launch_bounds__(512) k_gather(
    const float* __restrict__ x, const float* __restrict__ mem,
    const float* __restrict__ dt)
{
    int b = blockIdx.x, t = threadIdx.x, lane = t & 31, w = t >> 5;
    __shared__ float s_qk[INDIM];
    __shared__ float s_part[16][INDIM];
    __shared__ float s_m[16], s_l[16];

    if (t < INDIM) s_qk[t] = g_qk[(size_t)b * INDIM + t];
    __syncthreads();
    int cnt = g_cnt[b];
    const float scale = 0.08838834764831845f;   // 1/sqrt(128)

    float m = -INFINITY, l = 0.f;
    float racc[12];
    #pragma unroll
    for (int r = 0; r < 12; r++) racc[r] = 0.f;

    int p = w;
    float rowv[12];
    if (p < cnt) {
        int n = g_list[b * CAP + p];
        const float* px = x + (size_t)n * LAT;
        const float* pm = mem + (size_t)n * LAT;
        const float* pd = dt + (size_t)n * LAT;
        #pragma unroll
        for (int r = 0; r < 4; r++) rowv[r]     = px[lane + 32 * r];
        #pragma unroll
        for (int r = 0; r < 4; r++) rowv[4 + r] = pm[lane + 32 * r];
        #pragma unroll
        for (int r = 0; r < 4; r++) rowv[8 + r] = pd[lane + 32 * r];
    }
    while (p < cnt) {
        int pn = p + 16;
        float rnext[12];
        if (pn < cnt) {
            int n = g_list[b * CAP + pn];
            const float* px = x + (size_t)n * LAT;
            const float* pm = mem + (size_t)n * LAT;
            const float* pd = dt + (size_t)n * LAT;
            #pragma unroll
            for (int r = 0; r < 4; r++) rnext[r]     = px[lane + 32 * r];
            #pragma unroll
            for (int r = 0; r < 4; r++) rnext[4 + r] = pm[lane + 32 * r];
            #pragma unroll
            for (int r = 0; r < 4; r++) rnext[8 + r] = pd[lane + 32 * r];
        }
        float dot = 0.f;
        #pragma unroll
        for (int r = 0; r < 12; r++) dot = fmaf(rowv[r], s_qk[32 * r + lane], dot);
        #pragma unroll
        for (int off = 16; off; off >>= 1) dot += __shfl_xor_sync(0xffffffffu, dot, off);
        float s = dot * scale;                  // q.bk dropped (softmax-invariant)
        float mnew = fmaxf(m, s);
        float corr = __expf(m - mnew);
        float e = __expf(s - mnew);
        l = l * corr + e;
        m = mnew;
        #pragma unroll
        for (int r = 0; r < 12; r++) racc[r] = fmaf(racc[r], corr, e * rowv[r]);
        #pragma unroll
        for (int r = 0; r < 12; r++) rowv[r] = rnext[r];
        p = pn;
    }
    #pragma unroll
    for (int r = 0; r < 12; r++) s_part[w][32 * r + lane] = racc[r];
    if (lane == 0) { s_m[w] = m; s_l[w] = l; }
    __syncthreads();

    float M = s_m[0];
    #pragma unroll
    for (int i = 1; i < 16; i++) M = fmaxf(M, s_m[i]);
    float L = 0.f;
    float ef[16];
    #pragma unroll
    for (int i = 0; i < 16; i++) { ef[i] = __expf(s_m[i] - M); L += s_l[i] * ef[i]; }
    float invL = 1.f / L;
    if (t < INDIM) {
        float sum = 0.f;
        #pragma unroll
        for (int i = 0; i < 16; i++) sum = fmaf(s_part[i][t], ef[i], sum);
        g_acc[(size_t)b * INDIM + t] = sum * invL;
    }
}

// ---------------------------------------------------------------------------
// Kernel 3: folded epilogue — EQ=4 queries/block, 256 blocks x 512 thr.
// (R14 measured epi@GQ=8/128 blocks = 22us, occ 25% — grid < SM count.
//  256 blocks -> >=1.7 blocks/SM; one 4-query reduce group per output.)
//   h = relu(Wfold@acc + hpart + cvec) ; out = W2@h + b2
// ---------------------------------------------------------------------------
__global__ void __launch_bounds__(512, 2) k_epi(
    const float* __restrict__ W2, const float* __restrict__ b2,
    float* __restrict__ out)
{
    int b0 = blockIdx.x * EQ;
    int t = threadIdx.x, lane = t & 31, w = t >> 5;
    __shared__ float acc[EQ][INDIM];
    __shared__ float hp[EQ][LAT];
    __shared__ float h[EQ][LAT];

    for (int m = t; m < EQ * 96; m += 512) {
        int q = m / 96, c4 = m % 96;
        *(float4*)&acc[q][c4 * 4] = *(const float4*)&g_acc[(size_t)(b0 + q) * INDIM + c4 * 4];
    }
    for (int m = t; m < EQ * LAT; m += 512) {
        int q = m >> 7, o = m & 127;
        hp[q][o] = g_hpart[(size_t)(b0 + q) * LAT + o] + g_cvec[o];
    }
    __syncthreads();

    // stage 1: h = relu(Wfold @ acc + hp)  (one 4-query group)
    for (int oi = 0; oi < 8; oi++) {
        int o = w * 8 + oi;
        const float* wr = g_Wfold + (size_t)o * INDIM;
        float wreg[12];
        #pragma unroll
        for (int r = 0; r < 12; r++) wreg[r] = wr[lane + 32 * r];
        float p[EQ];
        #pragma unroll
        for (int qq = 0; qq < EQ; qq++) {
            float s = 0.f;
            #pragma unroll
            for (int r = 0; r < 12; r++)
                s = fmaf(wreg[r], acc[qq][lane + 32 * r], s);
            p[qq] = s;
        }
        float a0 = mrg(p[0], p[1], 16, lane), a1 = mrg(p[2], p[3], 16, lane);
        float c0 = mrg(a0, a1, 8, lane);
        c0 += __shfl_xor_sync(0xffffffffu, c0, 4);
        c0 += __shfl_xor_sync(0xffffffffu, c0, 2);
        c0 += __shfl_xor_sync(0xffffffffu, c0, 1);
        if ((lane & 7) == 0) {
            int q = ((lane >> 4) & 1) + ((lane >> 3) & 1) * 2;
            h[q][o] = fmaxf(c0 + hp[q][o], 0.f);
        }
    }
    __syncthreads();

    // stage 2: out = W2 @ h + b2  (one 4-query group)
    for (int oi = 0; oi < 8; oi++) {
        int o = w * 8 + oi;
        const float* wr = W2 + (size_t)o * LAT;
        float wreg[4];
        #pragma unroll
        for (int r = 0; r < 4; r++) wreg[r] = wr[lane + 32 * r];
        float bias = b2[o];
        float p[EQ];
        #pragma unroll
        for (int qq = 0; qq < EQ; qq++) {
            float s = 0.f;
            #pragma unroll
            for (int r = 0; r < 4; r++)
                s = fmaf(wreg[r], h[qq][lane + 32 * r], s);
            p[qq] = s;
        }
        float a0 = mrg(p[0], p[1], 16, lane), a1 = mrg(p[2], p[3], 16, lane);
        float c0 = mrg(a0, a1, 8, lane);
        c0 += __shfl_xor_sync(0xffffffffu, c0, 4);
        c0 += __shfl_xor_sync(0xffffffffu, c0, 2);
        c0 += __shfl_xor_sync(0xffffffffu, c0, 1);
        if ((lane & 7) == 0) {
            int q = ((lane >> 4) & 1) + ((lane >> 3) & 1) * 2;
            out[(size_t)(b0 + q) * LAT + o] = c0 + bias;
        }
    }
}

// ---------------------------------------------------------------------------
extern "C" void kernel_launch(void* const* d_in, const int* in_sizes, int n_in,
                              void* d_out, int out_size)
{
    const float* x    = (const float*)d_in[0];
    const float* mem  = (const float*)d_in[1];
    const float* dt   = (const float*)d_in[2];
    const float* tart = (const float*)d_in[3];
    const unsigned char* mask = (const unsigned char*)d_in[4];
    const int*   tidx = (const int*)d_in[5];
    const float* Wq = (const float*)d_in[6];
    const float* bq = (const float*)d_in[7];
    const float* Wk = (const float*)d_in[8];
    // bk (d_in[9]) unused: q.bk cancels in softmax
    const float* Wv = (const float*)d_in[10];
    const float* bv = (const float*)d_in[11];
    const float* W1 = (const float*)d_in[12];
    const float* b1 = (const float*)d_in[13];
    const float* W2 = (const float*)d_in[14];
    const float* b2 = (const float*)d_in[15];
    float* out = (float*)d_out;

    k_main<<<PREPB + BB, 512>>>(x, mem, tart, tidx, Wq, bq, Wk, W1, b1, Wv, bv, mask);
    k_gather<<<BB, 512>>>(x, mem, dt);
    k_epi<<<BB / EQ, 512>>>(W2, b2, out);
}